// round 7
// baseline (speedup 1.0000x reference)
#include <cuda_runtime.h>

#define FULL 0xFFFFFFFFu
#define NCAM 6
#define LWIN 36
#define QN   1536
#define KN   384
#define HL   144
#define DIMF 128
#define KEEPQ 1152
#define TOPK  96
#define SCALE_F 0.17677669529663687f

__device__ float QH[HL * QN * 32];
__device__ float KH[HL * KN * 32];
__device__ float VH[HL * KN * 32];
__device__ float AO[HL * QN * 32];
__device__ float SAL[HL * QN];
__device__ unsigned char QKEEP[HL * QN];
__device__ float PMEAN[HL * 32];

// ---------------------------------------------------------------------------
// Kernel 1: window rearrange + LayerNorm + 128x128 projection, warp per token.
// which: 0 -> QH (+SAL), 1 -> KH, 2 -> VH.
// ---------------------------------------------------------------------------
__global__ void proj_kernel(const float* __restrict__ in,
                            const float* __restrict__ gamma,
                            const float* __restrict__ beta,
                            const float* __restrict__ W,
                            const float* __restrict__ bias,
                            int tokPerL, int wsz, int which)
{
    extern __shared__ float Wsh[];
    for (int i = threadIdx.x; i < 128 * 128 / 4; i += blockDim.x)
        ((float4*)Wsh)[i] = ((const float4*)W)[i];
    __syncthreads();

    float* out = (which == 0) ? QH : (which == 1) ? KH : VH;

    const int lane = threadIdx.x & 31;
    const int wid  = threadIdx.x >> 5;
    const int nwarps = (blockDim.x >> 5) * gridDim.x;
    int gw = blockIdx.x * (blockDim.x >> 5) + wid;
    const float4* Wsh4 = (const float4*)Wsh;

    const float4 gm = ((const float4*)gamma)[lane];
    const float4 bt = ((const float4*)beta)[lane];
    const float4 bi = ((const float4*)bias)[lane];
    const int ww = wsz * wsz;
    const int h = lane >> 3, dh = (lane & 7) * 4;
    const int nTok = LWIN * tokPerL;

    for (int o = gw; o < nTok; o += nwarps) {
        int l = o / tokPerL, t = o - l * tokPerL;
        int n = t / ww, r = t - n * ww;
        int w1 = r / wsz, w2 = r - w1 * wsz;
        int x = l / 6, y = l - x * 6;
        int inIdx = ((((n * 6 + x) * 6 + y) * wsz + w1) * wsz + w2) * DIMF;

        float4 xv = ((const float4*)(in + inIdx))[lane];
        float s  = xv.x + xv.y + xv.z + xv.w;
        float ss = xv.x*xv.x + xv.y*xv.y + xv.z*xv.z + xv.w*xv.w;
        #pragma unroll
        for (int off = 16; off > 0; off >>= 1) {
            s  += __shfl_xor_sync(FULL, s,  off);
            ss += __shfl_xor_sync(FULL, ss, off);
        }
        float mu   = s * (1.f / 128.f);
        float var  = ss * (1.f / 128.f) - mu * mu;
        float rstd = rsqrtf(var + 1e-5f);

        float xn[4];
        xn[0] = (xv.x - mu) * rstd * gm.x + bt.x;
        xn[1] = (xv.y - mu) * rstd * gm.y + bt.y;
        xn[2] = (xv.z - mu) * rstd * gm.z + bt.z;
        xn[3] = (xv.w - mu) * rstd * gm.w + bt.w;

        float4 acc = bi;
        #pragma unroll 8
        for (int sl = 0; sl < 32; ++sl) {
            #pragma unroll
            for (int jj = 0; jj < 4; ++jj) {
                float xk = __shfl_sync(FULL, xn[jj], sl);
                float4 w = Wsh4[(sl * 4 + jj) * 32 + lane];
                acc.x = fmaf(xk, w.x, acc.x);
                acc.y = fmaf(xk, w.y, acc.y);
                acc.z = fmaf(xk, w.z, acc.z);
                acc.w = fmaf(xk, w.w, acc.w);
            }
        }
        ((float4*)(out + ((h * LWIN + l) * tokPerL + t) * 32 + dh))[0] = acc;

        if (which == 0) {
            float sq = acc.x*acc.x + acc.y*acc.y + acc.z*acc.z + acc.w*acc.w;
            sq += __shfl_down_sync(FULL, sq, 4, 8);
            sq += __shfl_down_sync(FULL, sq, 2, 8);
            sq += __shfl_down_sync(FULL, sq, 1, 8);
            if ((lane & 7) == 0)
                SAL[(h * LWIN + l) * tokPerL + t] = sq;
        }
    }
}

// ---------------------------------------------------------------------------
// Kernel 2: keep top-1152 of 1536 saliencies per (h,l), stable tie-break.
// ---------------------------------------------------------------------------
__global__ void qkeep_kernel()
{
    __shared__ unsigned keys[QN];
    __shared__ int wsum[8];
    __shared__ int totSh;
    const int tid = threadIdx.x;
    const int row = blockIdx.x;

    for (int i = tid; i < QN; i += 256) {
        unsigned u = __float_as_uint(SAL[row * QN + i]);
        keys[i] = (u & 0x80000000u) ? ~u : (u | 0x80000000u);
    }
    __syncthreads();

    unsigned T = 0;
    for (int b = 31; b >= 0; --b) {
        unsigned cand = T | (1u << b);
        unsigned c = 0;
        for (int i = tid; i < QN; i += 256) c += (keys[i] >= cand) ? 1u : 0u;
        c = __reduce_add_sync(FULL, c);
        if ((tid & 31) == 0) wsum[tid >> 5] = (int)c;
        __syncthreads();
        if (tid == 0) { int t2 = 0; for (int w = 0; w < 8; ++w) t2 += wsum[w]; totSh = t2; }
        __syncthreads();
        if (totSh >= KEEPQ) T = cand;
        __syncthreads();
    }
    {
        unsigned c = 0;
        for (int i = tid; i < QN; i += 256) c += (keys[i] > T) ? 1u : 0u;
        c = __reduce_add_sync(FULL, c);
        if ((tid & 31) == 0) wsum[tid >> 5] = (int)c;
        __syncthreads();
        if (tid == 0) { int t2 = 0; for (int w = 0; w < 8; ++w) t2 += wsum[w]; totSh = t2; }
        __syncthreads();
    }
    int rem = KEEPQ - totSh;
    for (int i = tid; i < QN; i += 256)
        QKEEP[row * QN + i] = (keys[i] > T) ? 1 : 0;
    __syncthreads();
    if (tid == 0) {
        int r = rem;
        for (int i = 0; i < QN && r > 0; ++i)
            if (keys[i] == T) { QKEEP[row * QN + i] = 1; --r; }
    }
}

// ---------------------------------------------------------------------------
// Kernel 3: pruned-query result = mean(VH[0:96]) per (h,l).
// ---------------------------------------------------------------------------
__global__ void pmean_kernel()
{
    const int hl = blockIdx.x, d = threadIdx.x;
    float s = 0.f;
    for (int k = 0; k < TOPK; ++k) s += VH[(hl * KN + k) * 32 + d];
    PMEAN[hl * 32 + d] = s * (1.f / (float)TOPK);
}

// ---------------------------------------------------------------------------
// Kernel 4: attention. One block per (h,l). Warp handles 4 queries; 12 k/lane.
// ---------------------------------------------------------------------------
__global__ void __launch_bounds__(256, 1) attn_kernel()
{
    extern __shared__ float sm[];
    float* Kt = sm;              // 32 x 388
    float* Vt = sm + 12416;      // 32 x 388
    float* AB = sm + 24832;      // 8 warps * 4 q * 384

    const int hl = blockIdx.x;
    const int tid = threadIdx.x, lane = tid & 31, wid = tid >> 5;

    for (int i = tid; i < KN * 32; i += 256) {
        int k = i >> 5, d = i & 31;
        Kt[d * 388 + k] = KH[hl * (KN * 32) + i];
        Vt[d * 388 + k] = VH[hl * (KN * 32) + i];
    }
    __syncthreads();

    const float pm = PMEAN[hl * 32 + lane];
    float* myAB = AB + wid * 1536;
    const unsigned lt = (1u << lane) - 1u;

    for (int g = wid; g < QN / 4; g += 8) {
        const int q0 = g * 4;
        float qreg[4];
        int kp[4];
        #pragma unroll
        for (int qq = 0; qq < 4; ++qq) {
            qreg[qq] = QH[(hl * QN + q0 + qq) * 32 + lane] * SCALE_F;
            kp[qq]   = QKEEP[hl * QN + q0 + qq];
        }

        float acc[4][12];
        #pragma unroll
        for (int qq = 0; qq < 4; ++qq)
            #pragma unroll
            for (int i = 0; i < 12; ++i) acc[qq][i] = 0.f;

        #pragma unroll 8
        for (int d = 0; d < 32; ++d) {
            const float4* kr = (const float4*)(Kt + d * 388 + lane * 12);
            float4 k0 = kr[0], k1 = kr[1], k2 = kr[2];
            float kv[12] = {k0.x,k0.y,k0.z,k0.w,k1.x,k1.y,k1.z,k1.w,k2.x,k2.y,k2.z,k2.w};
            #pragma unroll
            for (int qq = 0; qq < 4; ++qq) {
                float qb = __shfl_sync(FULL, qreg[qq], d);
                #pragma unroll
                for (int i = 0; i < 12; ++i)
                    acc[qq][i] = fmaf(qb, kv[i], acc[qq][i]);
            }
        }

        #pragma unroll 1
        for (int qq = 0; qq < 4; ++qq) {
            float4* dst = (float4*)(myAB + qq * 384 + lane * 12);
            if (!kp[qq]) {
                float4 z = make_float4(0.f,0.f,0.f,0.f);
                dst[0] = z; dst[1] = z; dst[2] = z;
                continue;
            }
            unsigned us[12];
            #pragma unroll
            for (int i = 0; i < 12; ++i) {
                unsigned u = __float_as_uint(acc[qq][i]);
                us[i] = (u & 0x80000000u) ? ~u : (u | 0x80000000u);
            }
            unsigned T = 0;
            for (int b = 31; b >= 0; --b) {
                unsigned cand = T | (1u << b);
                unsigned c = 0;
                #pragma unroll
                for (int i = 0; i < 12; ++i) c += (us[i] >= cand) ? 1u : 0u;
                c = __reduce_add_sync(FULL, c);
                if (c >= (unsigned)TOPK) T = cand;
            }
            unsigned cg = 0;
            #pragma unroll
            for (int i = 0; i < 12; ++i) cg += (us[i] > T) ? 1u : 0u;
            cg = __reduce_add_sync(FULL, cg);
            int rem = TOPK - (int)cg;
            int pre = 0;
            #pragma unroll
            for (int i = 0; i < 12; ++i) {
                unsigned m = __ballot_sync(FULL, us[i] == T);
                pre += __popc(m & lt);
            }
            float mx = -3.4e38f;
            #pragma unroll
            for (int i = 0; i < 12; ++i) mx = fmaxf(mx, acc[qq][i]);
            #pragma unroll
            for (int off = 16; off > 0; off >>= 1)
                mx = fmaxf(mx, __shfl_xor_sync(FULL, mx, off));

            float e[12];
            float ssum = 0.f;
            int cum = 0;
            #pragma unroll
            for (int i = 0; i < 12; ++i) {
                bool eq = (us[i] == T);
                bool keep = (us[i] > T) || (eq && (pre + cum) < rem);
                cum += eq ? 1 : 0;
                float ev = keep ? __expf(acc[qq][i] - mx) : 0.f;
                e[i] = ev;
                ssum += ev;
            }
            #pragma unroll
            for (int off = 16; off > 0; off >>= 1)
                ssum += __shfl_xor_sync(FULL, ssum, off);
            float inv = 1.f / ssum;
            #pragma unroll
            for (int i = 0; i < 12; ++i) e[i] *= inv;
            dst[0] = make_float4(e[0], e[1], e[2],  e[3]);
            dst[1] = make_float4(e[4], e[5], e[6],  e[7]);
            dst[2] = make_float4(e[8], e[9], e[10], e[11]);
        }
        __syncwarp();

        float o0 = 0.f, o1 = 0.f, o2 = 0.f, o3 = 0.f;
        const float4* vr  = (const float4*)(Vt + lane * 388);
        const float4* a0p = (const float4*)(myAB);
        const float4* a1p = (const float4*)(myAB + 384);
        const float4* a2p = (const float4*)(myAB + 768);
        const float4* a3p = (const float4*)(myAB + 1152);
        #pragma unroll 4
        for (int c = 0; c < KN / 4; ++c) {
            float4 v4 = vr[c];
            float4 a;
            a = a0p[c]; o0 += a.x*v4.x + a.y*v4.y + a.z*v4.z + a.w*v4.w;
            a = a1p[c]; o1 += a.x*v4.x + a.y*v4.y + a.z*v4.z + a.w*v4.w;
            a = a2p[c]; o2 += a.x*v4.x + a.y*v4.y + a.z*v4.z + a.w*v4.w;
            a = a3p[c]; o3 += a.x*v4.x + a.y*v4.y + a.z*v4.z + a.w*v4.w;
        }
        __syncwarp();

        float outs[4] = {o0, o1, o2, o3};
        #pragma unroll
        for (int qq = 0; qq < 4; ++qq)
            AO[(hl * QN + q0 + qq) * 32 + lane] = kp[qq] ? outs[qq] : pm;
    }
}

// ---------------------------------------------------------------------------
// Kernel 5: camera-mean -> output projection -> + bp + skip. Warp per token.
// ---------------------------------------------------------------------------
__global__ void final_kernel(const float* __restrict__ skip,
                             const float* __restrict__ Wp,
                             const float* __restrict__ bp,
                             float* __restrict__ outp)
{
    extern __shared__ float Wsh[];
    for (int i = threadIdx.x; i < 128 * 128 / 4; i += blockDim.x)
        ((float4*)Wsh)[i] = ((const float4*)Wp)[i];
    __syncthreads();

    const int lane = threadIdx.x & 31;
    const int wid  = threadIdx.x >> 5;
    const int nwarps = (blockDim.x >> 5) * gridDim.x;
    int gw = blockIdx.x * (blockDim.x >> 5) + wid;
    const float4* Wsh4 = (const float4*)Wsh;
    const float4 bi = ((const float4*)bp)[lane];
    const int h = lane >> 3, dbase = (lane & 7) * 4;

    for (int o = gw; o < LWIN * 256; o += nwarps) {
        int l = o >> 8, rr = o & 255;
        float4 ab = make_float4(0.f,0.f,0.f,0.f);
        #pragma unroll
        for (int n = 0; n < NCAM; ++n) {
            float4 t = ((const float4*)(AO + ((h * LWIN + l) * QN + n * 256 + rr) * 32 + dbase))[0];
            ab.x += t.x; ab.y += t.y; ab.z += t.z; ab.w += t.w;
        }
        const float inv6 = 1.f / 6.f;
        float xn[4] = {ab.x*inv6, ab.y*inv6, ab.z*inv6, ab.w*inv6};

        float4 acc = bi;
        #pragma unroll 8
        for (int sl = 0; sl < 32; ++sl) {
            #pragma unroll
            for (int jj = 0; jj < 4; ++jj) {
                float xk = __shfl_sync(FULL, xn[jj], sl);
                float4 w = Wsh4[(sl * 4 + jj) * 32 + lane];
                acc.x = fmaf(xk, w.x, acc.x);
                acc.y = fmaf(xk, w.y, acc.y);
                acc.z = fmaf(xk, w.z, acc.z);
                acc.w = fmaf(xk, w.w, acc.w);
            }
        }
        float4 sk = ((const float4*)(skip + o * DIMF))[lane];
        acc.x += sk.x; acc.y += sk.y; acc.z += sk.z; acc.w += sk.w;
        ((float4*)(outp + o * DIMF))[lane] = acc;
    }
}

// ---------------------------------------------------------------------------
// Inputs: 0 q, 1 k, 2 v, 3 skip, 4 logit_bias (dead), 5 g_q, 6 b_q, 7 g_k,
// 8 b_k, 9 g_v, 10 b_v, 11 Wq, 12 bq, 13 Wk, 14 bk, 15 Wv, 16 bv, 17 Wp, 18 bp
// ---------------------------------------------------------------------------
extern "C" void kernel_launch(void* const* d_in, const int* in_sizes, int n_in,
                              void* d_out, int out_size)
{
    const float* q    = (const float*)d_in[0];
    const float* k    = (const float*)d_in[1];
    const float* v    = (const float*)d_in[2];
    const float* skip = (const float*)d_in[3];
    const float* g_q  = (const float*)d_in[5];
    const float* b_q  = (const float*)d_in[6];
    const float* g_k  = (const float*)d_in[7];
    const float* b_k  = (const float*)d_in[8];
    const float* g_v  = (const float*)d_in[9];
    const float* b_v  = (const float*)d_in[10];
    const float* Wq   = (const float*)d_in[11];
    const float* bq   = (const float*)d_in[12];
    const float* Wk   = (const float*)d_in[13];
    const float* bk   = (const float*)d_in[14];
    const float* Wv   = (const float*)d_in[15];
    const float* bv   = (const float*)d_in[16];
    const float* Wp   = (const float*)d_in[17];
    const float* bp   = (const float*)d_in[18];
    float* outp = (float*)d_out;

    cudaFuncSetAttribute(proj_kernel,  cudaFuncAttributeMaxDynamicSharedMemorySize, 65536);
    cudaFuncSetAttribute(attn_kernel,  cudaFuncAttributeMaxDynamicSharedMemorySize, 148480);
    cudaFuncSetAttribute(final_kernel, cudaFuncAttributeMaxDynamicSharedMemorySize, 65536);

    proj_kernel<<<148, 256, 65536>>>(q, g_q, b_q, Wq, bq, QN, 16, 0);
    proj_kernel<<<148, 256, 65536>>>(k, g_k, b_k, Wk, bk, KN, 8, 1);
    proj_kernel<<<148, 256, 65536>>>(v, g_v, b_v, Wv, bv, KN, 8, 2);
    qkeep_kernel<<<HL, 256>>>();
    pmean_kernel<<<HL, 32>>>();
    attn_kernel<<<HL, 256, 148480>>>();
    final_kernel<<<148, 256, 65536>>>(skip, Wp, bp, outp);
}